// round 1
// baseline (speedup 1.0000x reference)
#include <cuda_runtime.h>
#include <math.h>

#define B_SZ     4
#define T_LEN    1024
#define S_LEN    4096
#define D_MODEL  1024
#define NUM_HEADS 16
#define HEAD_DIM  64
#define AP        68   // smem pitch (floats) for attention tiles

// ---------------- scratch (no allocations allowed) ----------------
__device__ float g_Q [(size_t)B_SZ * T_LEN * D_MODEL];   // 16.8 MB
__device__ float g_K [(size_t)B_SZ * S_LEN * D_MODEL];   // 67 MB
__device__ float g_V [(size_t)B_SZ * S_LEN * D_MODEL];   // 67 MB
__device__ float g_AO[(size_t)B_SZ * T_LEN * D_MODEL];   // 16.8 MB

// =================================================================
// C[M,1024] = A[M,1024] @ W[1024,1024]^T + bias
// src_sel: 0 -> A_ext, 1 -> g_AO
// dst_sel: 0 -> g_Q, 1 -> g_K, 2 -> g_V, 3 -> C_ext
// Tiles: BM=BN=128, BK=16, 256 threads, 8x8 per thread.
// =================================================================
__global__ __launch_bounds__(256) void gemm_nt_bias(
    const float* __restrict__ A_ext, int src_sel,
    const float* __restrict__ W, const float* __restrict__ bias,
    float* __restrict__ C_ext, int dst_sel, int M)
{
    const int K = 1024, N = 1024;
    const float* A = (src_sel == 1) ? g_AO : A_ext;
    float* C = (dst_sel == 0) ? g_Q
             : (dst_sel == 1) ? g_K
             : (dst_sel == 2) ? g_V : C_ext;

    __shared__ float As[16][128];   // [k][m]
    __shared__ float Ws[16][128];   // [k][n]

    const int tid = threadIdx.x;
    const int bm  = blockIdx.y * 128;
    const int bn  = blockIdx.x * 128;
    const int tx  = tid & 15;        // 0..15
    const int ty  = tid >> 4;        // 0..15
    const int tm0 = ty * 8;
    const int tn0 = tx * 8;
    const int lrow = tid >> 2;       // 0..63
    const int lc4  = tid & 3;        // 0..3

    float acc[8][8];
    #pragma unroll
    for (int m = 0; m < 8; m++)
        #pragma unroll
        for (int n = 0; n < 8; n++) acc[m][n] = 0.f;

    const float* Aptr = A + (size_t)bm * K;
    const float* Wptr = W + (size_t)bn * K;

    for (int k0 = 0; k0 < K; k0 += 16) {
        #pragma unroll
        for (int i = 0; i < 2; i++) {
            int r = lrow + i * 64;
            float4 va = *reinterpret_cast<const float4*>(Aptr + (size_t)r * K + k0 + lc4 * 4);
            As[lc4*4+0][r] = va.x; As[lc4*4+1][r] = va.y;
            As[lc4*4+2][r] = va.z; As[lc4*4+3][r] = va.w;
            float4 vw = *reinterpret_cast<const float4*>(Wptr + (size_t)r * K + k0 + lc4 * 4);
            Ws[lc4*4+0][r] = vw.x; Ws[lc4*4+1][r] = vw.y;
            Ws[lc4*4+2][r] = vw.z; Ws[lc4*4+3][r] = vw.w;
        }
        __syncthreads();

        #pragma unroll
        for (int k = 0; k < 16; k++) {
            float a[8], b[8];
            *reinterpret_cast<float4*>(&a[0]) = *reinterpret_cast<const float4*>(&As[k][tm0]);
            *reinterpret_cast<float4*>(&a[4]) = *reinterpret_cast<const float4*>(&As[k][tm0 + 4]);
            *reinterpret_cast<float4*>(&b[0]) = *reinterpret_cast<const float4*>(&Ws[k][tn0]);
            *reinterpret_cast<float4*>(&b[4]) = *reinterpret_cast<const float4*>(&Ws[k][tn0 + 4]);
            #pragma unroll
            for (int m = 0; m < 8; m++)
                #pragma unroll
                for (int n = 0; n < 8; n++)
                    acc[m][n] += a[m] * b[n];
        }
        __syncthreads();
    }

    #pragma unroll
    for (int m = 0; m < 8; m++) {
        size_t row = (size_t)(bm + tm0 + m);
        #pragma unroll
        for (int n = 0; n < 8; n += 4) {
            float4 bv = *reinterpret_cast<const float4*>(&bias[bn + tn0 + n]);
            float4 o;
            o.x = acc[m][n+0] + bv.x;
            o.y = acc[m][n+1] + bv.y;
            o.z = acc[m][n+2] + bv.z;
            o.w = acc[m][n+3] + bv.w;
            *reinterpret_cast<float4*>(&C[row * N + bn + tn0 + n]) = o;
        }
    }
}

// =================================================================
// Flash attention per (b, h, 64-query tile). Strided KV gather.
// Block: 128 threads. Tiles of 64 keys. Online softmax.
// smem: sQ[d][r] (transposed), sK[d][c] (transposed), sV[j][d], sS[r][j]
// =================================================================
__global__ __launch_bounds__(128) void attention_kernel()
{
    extern __shared__ float sm[];
    float* sQ = sm;                 // [64][AP], d-major
    float* sK = sQ + 64 * AP;       // [64][AP], d-major
    float* sV = sK + 64 * AP;       // [64][AP], key-major
    float* sS = sV + 64 * AP;       // [64][AP], row-major
    float* row_m     = sS + 64 * AP;
    float* row_l     = row_m + 64;
    float* row_alpha = row_l + 64;

    const int tid = threadIdx.x;
    const int b   = blockIdx.z;
    const int h   = blockIdx.y;
    const int q0  = blockIdx.x * 64;
    const int s   = 1 << (h & 3);          // STRIDE_LIST = [1,2,4,8] repeating
    const int Sh  = S_LEN / s;
    const int ntiles = Sh / 64;
    const int tx = tid & 7;                 // 0..7  -> 8-col group
    const int ty = tid >> 3;                // 0..15 -> 4-row group
    const int r0 = ty * 4;
    const int c0 = tx * 8;

    // ---- load Q tile (scaled by 1/sqrt(hd)) transposed into sQ ----
    {
        const float* Qg = g_Q + ((size_t)b * T_LEN + q0) * D_MODEL + h * HEAD_DIM;
        #pragma unroll
        for (int i = 0; i < 8; i++) {
            int idx = tid + i * 128;
            int r   = idx >> 4;
            int d0  = (idx & 15) * 4;
            float4 v = *reinterpret_cast<const float4*>(Qg + (size_t)r * D_MODEL + d0);
            sQ[(d0+0)*AP + r] = v.x * 0.125f;
            sQ[(d0+1)*AP + r] = v.y * 0.125f;
            sQ[(d0+2)*AP + r] = v.z * 0.125f;
            sQ[(d0+3)*AP + r] = v.w * 0.125f;
        }
    }
    if (tid < 64) { row_m[tid] = -1e30f; row_l[tid] = 0.f; }

    float acc[4][8];
    #pragma unroll
    for (int m = 0; m < 4; m++)
        #pragma unroll
        for (int n = 0; n < 8; n++) acc[m][n] = 0.f;

    const float* Kg = g_K + (size_t)b * S_LEN * D_MODEL + h * HEAD_DIM;
    const float* Vg = g_V + (size_t)b * S_LEN * D_MODEL + h * HEAD_DIM;

    for (int t = 0; t < ntiles; t++) {
        const int j0 = t * 64;

        // ---- load K (transposed) + V tiles, strided gather ----
        #pragma unroll
        for (int i = 0; i < 8; i++) {
            int idx = tid + i * 128;
            int j   = idx >> 4;
            int d0  = (idx & 15) * 4;
            size_t goff = (size_t)(j0 + j) * s * D_MODEL + d0;
            float4 kv = *reinterpret_cast<const float4*>(Kg + goff);
            sK[(d0+0)*AP + j] = kv.x;
            sK[(d0+1)*AP + j] = kv.y;
            sK[(d0+2)*AP + j] = kv.z;
            sK[(d0+3)*AP + j] = kv.w;
            float4 vv = *reinterpret_cast<const float4*>(Vg + goff);
            *reinterpret_cast<float4*>(&sV[j * AP + d0]) = vv;
        }
        __syncthreads();

        // ---- S = (Q*scale) @ K^T  (4x8 per thread) ----
        float sacc[4][8];
        #pragma unroll
        for (int m = 0; m < 4; m++)
            #pragma unroll
            for (int n = 0; n < 8; n++) sacc[m][n] = 0.f;

        #pragma unroll 8
        for (int d = 0; d < 64; d++) {
            float4 q  = *reinterpret_cast<const float4*>(&sQ[d * AP + r0]);
            float4 k0 = *reinterpret_cast<const float4*>(&sK[d * AP + c0]);
            float4 k1 = *reinterpret_cast<const float4*>(&sK[d * AP + c0 + 4]);
            float qa[4] = {q.x, q.y, q.z, q.w};
            float kb[8] = {k0.x, k0.y, k0.z, k0.w, k1.x, k1.y, k1.z, k1.w};
            #pragma unroll
            for (int m = 0; m < 4; m++)
                #pragma unroll
                for (int n = 0; n < 8; n++)
                    sacc[m][n] += qa[m] * kb[n];
        }
        #pragma unroll
        for (int m = 0; m < 4; m++) {
            float4 o0 = {sacc[m][0], sacc[m][1], sacc[m][2], sacc[m][3]};
            float4 o1 = {sacc[m][4], sacc[m][5], sacc[m][6], sacc[m][7]};
            *reinterpret_cast<float4*>(&sS[(r0+m) * AP + c0    ]) = o0;
            *reinterpret_cast<float4*>(&sS[(r0+m) * AP + c0 + 4]) = o1;
        }
        __syncthreads();

        // ---- online softmax (one thread per row) ----
        if (tid < 64) {
            float* srow = sS + tid * AP;
            float mx = -1e30f;
            #pragma unroll 8
            for (int j = 0; j < 64; j++) mx = fmaxf(mx, srow[j]);
            float mo = row_m[tid];
            float mn = fmaxf(mo, mx);
            float alpha = __expf(mo - mn);
            float sum = 0.f;
            #pragma unroll 8
            for (int j = 0; j < 64; j++) {
                float p = __expf(srow[j] - mn);
                srow[j] = p;
                sum += p;
            }
            row_l[tid] = row_l[tid] * alpha + sum;
            row_m[tid] = mn;
            row_alpha[tid] = alpha;
        }
        __syncthreads();

        // ---- rescale accumulator, then acc += P @ V ----
        float al[4];
        #pragma unroll
        for (int m = 0; m < 4; m++) al[m] = row_alpha[r0 + m];
        #pragma unroll
        for (int m = 0; m < 4; m++)
            #pragma unroll
            for (int n = 0; n < 8; n++) acc[m][n] *= al[m];

        #pragma unroll 8
        for (int j = 0; j < 64; j++) {
            float p[4];
            #pragma unroll
            for (int m = 0; m < 4; m++) p[m] = sS[(r0+m) * AP + j];
            float4 v0 = *reinterpret_cast<const float4*>(&sV[j * AP + c0]);
            float4 v1 = *reinterpret_cast<const float4*>(&sV[j * AP + c0 + 4]);
            float vb[8] = {v0.x, v0.y, v0.z, v0.w, v1.x, v1.y, v1.z, v1.w};
            #pragma unroll
            for (int m = 0; m < 4; m++)
                #pragma unroll
                for (int n = 0; n < 8; n++)
                    acc[m][n] += p[m] * vb[n];
        }
        __syncthreads();
    }

    // ---- epilogue: normalize, write to g_AO ----
    float* Og = g_AO + ((size_t)b * T_LEN + q0) * D_MODEL + h * HEAD_DIM;
    #pragma unroll
    for (int m = 0; m < 4; m++) {
        int r = r0 + m;
        float inv = 1.0f / row_l[r];
        float4 o0, o1;
        o0.x = acc[m][0]*inv; o0.y = acc[m][1]*inv; o0.z = acc[m][2]*inv; o0.w = acc[m][3]*inv;
        o1.x = acc[m][4]*inv; o1.y = acc[m][5]*inv; o1.z = acc[m][6]*inv; o1.w = acc[m][7]*inv;
        *reinterpret_cast<float4*>(Og + (size_t)r * D_MODEL + c0    ) = o0;
        *reinterpret_cast<float4*>(Og + (size_t)r * D_MODEL + c0 + 4) = o1;
    }
}

// =================================================================
extern "C" void kernel_launch(void* const* d_in, const int* in_sizes, int n_in,
                              void* d_out, int out_size)
{
    const float* dec = (const float*)d_in[0];
    const float* enc = (const float*)d_in[1];
    const float* Wq  = (const float*)d_in[2];
    const float* bq  = (const float*)d_in[3];
    const float* Wk  = (const float*)d_in[4];
    const float* bk  = (const float*)d_in[5];
    const float* Wv  = (const float*)d_in[6];
    const float* bv  = (const float*)d_in[7];
    const float* Wo  = (const float*)d_in[8];
    const float* bo  = (const float*)d_in[9];
    float* out = (float*)d_out;

    const int ATTN_SMEM = (4 * 64 * AP + 192) * (int)sizeof(float);   // 70400 B
    cudaFuncSetAttribute(attention_kernel,
                         cudaFuncAttributeMaxDynamicSharedMemorySize, ATTN_SMEM);

    // Q = dec @ Wq^T + bq   (M = 4096)
    gemm_nt_bias<<<dim3(8, 32),  256>>>(dec, 0, Wq, bq, nullptr, 0, B_SZ * T_LEN);
    // K = enc @ Wk^T + bk   (M = 16384)
    gemm_nt_bias<<<dim3(8, 128), 256>>>(enc, 0, Wk, bk, nullptr, 1, B_SZ * S_LEN);
    // V = enc @ Wv^T + bv
    gemm_nt_bias<<<dim3(8, 128), 256>>>(enc, 0, Wv, bv, nullptr, 2, B_SZ * S_LEN);
    // strided multi-head cross attention -> g_AO
    attention_kernel<<<dim3(T_LEN / 64, NUM_HEADS, B_SZ), 128, ATTN_SMEM>>>();
    // out = AO @ Wo^T + bo
    gemm_nt_bias<<<dim3(8, 32),  256>>>(nullptr, 1, Wo, bo, out, 3, B_SZ * T_LEN);
}

// round 3
// speedup vs baseline: 1.4506x; 1.4506x over previous
#include <cuda_runtime.h>
#include <cuda_bf16.h>
#include <cstdint>
#include <math.h>

#define B_SZ     4
#define T_LEN    1024
#define S_LEN    4096
#define D_MODEL  1024
#define NUM_HEADS 16
#define HEAD_DIM  64
#define AP        68

// ======================= scratch =======================
__device__ float g_Q [(size_t)B_SZ * T_LEN * D_MODEL];
__device__ float g_K [(size_t)B_SZ * S_LEN * D_MODEL];
__device__ float g_V [(size_t)B_SZ * S_LEN * D_MODEL];
__device__ float g_AO[(size_t)B_SZ * T_LEN * D_MODEL];
// hi/lo bf16: [rows][2048]  (cols 0..1023 = hi, 1024..2047 = lo)
__device__ __nv_bfloat16 g_dec2[(size_t)B_SZ * T_LEN * 2048];
__device__ __nv_bfloat16 g_enc2[(size_t)B_SZ * S_LEN * 2048];
__device__ __nv_bfloat16 g_ao2 [(size_t)B_SZ * T_LEN * 2048];
__device__ __nv_bfloat16 g_w2[4][(size_t)D_MODEL * 2048];

// ======================= helpers =======================
__device__ __forceinline__ uint32_t smem_to_u32(const void* p) {
    uint32_t a;
    asm("{ .reg .u64 t; cvta.to.shared.u64 t, %1; cvt.u32.u64 %0, t; }" : "=r"(a) : "l"(p));
    return a;
}
#define CP_ASYNC16(dst_u32, gptr) \
    asm volatile("cp.async.cg.shared.global [%0], [%1], 16;" :: "r"(dst_u32), "l"(gptr))
#define CP_COMMIT() asm volatile("cp.async.commit_group;" ::: "memory")

__device__ __forceinline__ void mma_bf16(float* c, const uint32_t* a, const uint32_t* b) {
    asm volatile(
        "mma.sync.aligned.m16n8k16.row.col.f32.bf16.bf16.f32 "
        "{%0,%1,%2,%3}, {%4,%5,%6,%7}, {%8,%9}, {%0,%1,%2,%3};"
        : "+f"(c[0]), "+f"(c[1]), "+f"(c[2]), "+f"(c[3])
        : "r"(a[0]), "r"(a[1]), "r"(a[2]), "r"(a[3]), "r"(b[0]), "r"(b[1]));
}
__device__ __forceinline__ void ldmatrix_x4(uint32_t* r, uint32_t addr) {
    asm volatile("ldmatrix.sync.aligned.m8n8.x4.shared.b16 {%0,%1,%2,%3}, [%4];"
        : "=r"(r[0]), "=r"(r[1]), "=r"(r[2]), "=r"(r[3]) : "r"(addr));
}

// ======================= fp32 -> hi/lo bf16 =======================
__global__ __launch_bounds__(256) void conv_hilo(
    const float* __restrict__ src_ext, int src_is_ao, int dst_sel, int total)
{
    const float* src = src_is_ao ? g_AO : src_ext;
    __nv_bfloat16* dst =
        (dst_sel == 0) ? g_dec2 :
        (dst_sel == 1) ? g_enc2 :
        (dst_sel == 2) ? g_ao2  : g_w2[dst_sel - 3];
    int i4 = blockIdx.x * blockDim.x + threadIdx.x;
    int i = i4 * 4;
    if (i >= total) return;
    int r = i >> 10;
    int k = i & 1023;
    float4 v = *reinterpret_cast<const float4*>(src + i);
    __nv_bfloat16 h0 = __float2bfloat16(v.x);
    __nv_bfloat16 h1 = __float2bfloat16(v.y);
    __nv_bfloat16 h2 = __float2bfloat16(v.z);
    __nv_bfloat16 h3 = __float2bfloat16(v.w);
    __nv_bfloat16 l0 = __float2bfloat16(v.x - __bfloat162float(h0));
    __nv_bfloat16 l1 = __float2bfloat16(v.y - __bfloat162float(h1));
    __nv_bfloat16 l2 = __float2bfloat16(v.z - __bfloat162float(h2));
    __nv_bfloat16 l3 = __float2bfloat16(v.w - __bfloat162float(h3));
    size_t base = (size_t)r * 2048 + k;
    ushort4 hv = { *(unsigned short*)&h0, *(unsigned short*)&h1,
                   *(unsigned short*)&h2, *(unsigned short*)&h3 };
    ushort4 lv = { *(unsigned short*)&l0, *(unsigned short*)&l1,
                   *(unsigned short*)&l2, *(unsigned short*)&l3 };
    *reinterpret_cast<ushort4*>(dst + base)        = hv;
    *reinterpret_cast<ushort4*>(dst + base + 1024) = lv;
}

// ======================= mma.sync GEMM =======================
// C[M,1024] = A[M,1024] @ W[1024,1024]^T + bias via bf16 hi/lo (3 products).
// CTA: 256 thr, tile M=128 N=256 BK=64; warp = 64x64; 48 k-iters.
// smem pitch = 72 halves (144 B) per row for both A and B tiles.
#define APITCH 72
#define A_TILE_B (128 * APITCH * 2)            // 18432
#define B_TILE_B (256 * APITCH * 2)            // 36864
#define STAGE_B  (A_TILE_B + B_TILE_B)         // 55296

__global__ __launch_bounds__(256) void gemm_mma(
    int src_sel, int w_sel, const float* __restrict__ bias,
    float* __restrict__ C_ext, int dst_sel)
{
    extern __shared__ char smem[];
    const __nv_bfloat16* A2 = (src_sel == 0) ? g_dec2 : (src_sel == 1) ? g_enc2 : g_ao2;
    const __nv_bfloat16* W2 = g_w2[w_sel];
    float* C = (dst_sel == 0) ? g_Q : (dst_sel == 1) ? g_K
             : (dst_sel == 2) ? g_V : C_ext;

    const int tid  = threadIdx.x;
    const int wid  = tid >> 5;
    const int lane = tid & 31;
    const int wm   = wid >> 2;          // 0..1
    const int wn   = wid & 3;           // 0..3
    const int bm   = blockIdx.y * 128;
    const int bn   = blockIdx.x * 256;
    const uint32_t sb = smem_to_u32(smem);

    float c[4][8][4];
    #pragma unroll
    for (int fm = 0; fm < 4; fm++)
        #pragma unroll
        for (int fn = 0; fn < 8; fn++)
            #pragma unroll
            for (int e = 0; e < 4; e++) c[fm][fn][e] = 0.f;

    const __nv_bfloat16* Abase = A2 + (size_t)bm * 2048;
    const __nv_bfloat16* Bbase = W2 + (size_t)bn * 2048;

    // --- tile loader: A 128x64, B 256x64 (halves), cp.async 16B ---
    auto load_tile = [&](int stage, int colA, int colB) {
        uint32_t sA = sb + stage * STAGE_B;
        uint32_t sB = sA + A_TILE_B;
        const int r0 = tid >> 3;        // 0..31
        const int c8 = tid & 7;         // 0..7  (x8 halves)
        #pragma unroll
        for (int i = 0; i < 4; i++) {   // A: 128 rows
            int r = r0 + i * 32;
            CP_ASYNC16(sA + r * 144 + c8 * 16,
                       Abase + (size_t)r * 2048 + colA + c8 * 8);
        }
        #pragma unroll
        for (int i = 0; i < 8; i++) {   // B: 256 rows
            int r = r0 + i * 32;
            CP_ASYNC16(sB + r * 144 + c8 * 16,
                       Bbase + (size_t)r * 2048 + colB + c8 * 8);
        }
    };

    load_tile(0, 0, 0);
    CP_COMMIT();

    const int NITER = 48;
    for (int i = 0; i < NITER; i++) {
        if (i + 1 < NITER) {
            int ni = i + 1, seg = ni >> 4, t = ni & 15;
            load_tile(ni & 1, (seg == 2 ? 1024 : 0) + t * 64,
                              (seg == 1 ? 1024 : 0) + t * 64);
            CP_COMMIT();
            asm volatile("cp.async.wait_group 1;" ::: "memory");
        } else {
            asm volatile("cp.async.wait_group 0;" ::: "memory");
        }
        __syncthreads();

        uint32_t sA = sb + (i & 1) * STAGE_B;
        uint32_t sB = sA + A_TILE_B;
        // A ldmatrix address base (per-lane): row = wm*64 + fm*16 + lane%16
        uint32_t aAddr = sA + (wm * 64 + (lane & 15)) * 144 + (lane >> 4) * 16;
        // B direct: n = wn*64 + fn*8 + lane/4 ; k word = lane%4
        uint32_t bRow = sB + (wn * 64 + (lane >> 2)) * 144 + (lane & 3) * 4;

        #pragma unroll
        for (int kt = 0; kt < 4; kt++) {
            uint32_t a[4][4];
            #pragma unroll
            for (int fm = 0; fm < 4; fm++)
                ldmatrix_x4(a[fm], aAddr + fm * 16 * 144 + kt * 32);
            uint32_t b[8][2];
            #pragma unroll
            for (int fn = 0; fn < 8; fn++) {
                uint32_t ba = bRow + fn * 8 * 144 + kt * 32;
                asm volatile("ld.shared.b32 %0, [%1];" : "=r"(b[fn][0]) : "r"(ba));
                asm volatile("ld.shared.b32 %0, [%1];" : "=r"(b[fn][1]) : "r"(ba + 16));
            }
            #pragma unroll
            for (int fm = 0; fm < 4; fm++)
                #pragma unroll
                for (int fn = 0; fn < 8; fn++)
                    mma_bf16(c[fm][fn], a[fm], b[fn]);
        }
        __syncthreads();
    }

    // --- epilogue: bias + store ---
    const int rBase = bm + wm * 64 + (lane >> 2);
    const int cBase = bn + wn * 64 + (lane & 3) * 2;
    #pragma unroll
    for (int fm = 0; fm < 4; fm++) {
        #pragma unroll
        for (int fn = 0; fn < 8; fn++) {
            int col = cBase + fn * 8;
            float2 bv = *reinterpret_cast<const float2*>(bias + col);
            int r0 = rBase + fm * 16;
            float2 o0 = { c[fm][fn][0] + bv.x, c[fm][fn][1] + bv.y };
            float2 o1 = { c[fm][fn][2] + bv.x, c[fm][fn][3] + bv.y };
            *reinterpret_cast<float2*>(C + (size_t)r0 * D_MODEL + col)       = o0;
            *reinterpret_cast<float2*>(C + (size_t)(r0 + 8) * D_MODEL + col) = o1;
        }
    }
}

// ======================= attention (unchanged) =======================
__global__ __launch_bounds__(128) void attention_kernel()
{
    extern __shared__ float sm[];
    float* sQ = sm;
    float* sK = sQ + 64 * AP;
    float* sV = sK + 64 * AP;
    float* sS = sV + 64 * AP;
    float* row_m     = sS + 64 * AP;
    float* row_l     = row_m + 64;
    float* row_alpha = row_l + 64;

    const int tid = threadIdx.x;
    const int b   = blockIdx.z;
    const int h   = blockIdx.y;
    const int q0  = blockIdx.x * 64;
    const int s   = 1 << (h & 3);
    const int Sh  = S_LEN / s;
    const int ntiles = Sh / 64;
    const int tx = tid & 7;
    const int ty = tid >> 3;
    const int r0 = ty * 4;
    const int c0 = tx * 8;

    {
        const float* Qg = g_Q + ((size_t)b * T_LEN + q0) * D_MODEL + h * HEAD_DIM;
        #pragma unroll
        for (int i = 0; i < 8; i++) {
            int idx = tid + i * 128;
            int r   = idx >> 4;
            int d0  = (idx & 15) * 4;
            float4 v = *reinterpret_cast<const float4*>(Qg + (size_t)r * D_MODEL + d0);
            sQ[(d0+0)*AP + r] = v.x * 0.125f;
            sQ[(d0+1)*AP + r] = v.y * 0.125f;
            sQ[(d0+2)*AP + r] = v.z * 0.125f;
            sQ[(d0+3)*AP + r] = v.w * 0.125f;
        }
    }
    if (tid < 64) { row_m[tid] = -1e30f; row_l[tid] = 0.f; }

    float acc[4][8];
    #pragma unroll
    for (int m = 0; m < 4; m++)
        #pragma unroll
        for (int n = 0; n < 8; n++) acc[m][n] = 0.f;

    const float* Kg = g_K + (size_t)b * S_LEN * D_MODEL + h * HEAD_DIM;
    const float* Vg = g_V + (size_t)b * S_LEN * D_MODEL + h * HEAD_DIM;

    for (int t = 0; t < ntiles; t++) {
        const int j0 = t * 64;
        #pragma unroll
        for (int i = 0; i < 8; i++) {
            int idx = tid + i * 128;
            int j   = idx >> 4;
            int d0  = (idx & 15) * 4;
            size_t goff = (size_t)(j0 + j) * s * D_MODEL + d0;
            float4 kv = *reinterpret_cast<const float4*>(Kg + goff);
            sK[(d0+0)*AP + j] = kv.x;
            sK[(d0+1)*AP + j] = kv.y;
            sK[(d0+2)*AP + j] = kv.z;
            sK[(d0+3)*AP + j] = kv.w;
            float4 vv = *reinterpret_cast<const float4*>(Vg + goff);
            *reinterpret_cast<float4*>(&sV[j * AP + d0]) = vv;
        }
        __syncthreads();

        float sacc[4][8];
        #pragma unroll
        for (int m = 0; m < 4; m++)
            #pragma unroll
            for (int n = 0; n < 8; n++) sacc[m][n] = 0.f;

        #pragma unroll 8
        for (int d = 0; d < 64; d++) {
            float4 q  = *reinterpret_cast<const float4*>(&sQ[d * AP + r0]);
            float4 k0 = *reinterpret_cast<const float4*>(&sK[d * AP + c0]);
            float4 k1 = *reinterpret_cast<const float4*>(&sK[d * AP + c0 + 4]);
            float qa[4] = {q.x, q.y, q.z, q.w};
            float kb[8] = {k0.x, k0.y, k0.z, k0.w, k1.x, k1.y, k1.z, k1.w};
            #pragma unroll
            for (int m = 0; m < 4; m++)
                #pragma unroll
                for (int n = 0; n < 8; n++)
                    sacc[m][n] += qa[m] * kb[n];
        }
        #pragma unroll
        for (int m = 0; m < 4; m++) {
            float4 o0 = {sacc[m][0], sacc[m][1], sacc[m][2], sacc[m][3]};
            float4 o1 = {sacc[m][4], sacc[m][5], sacc[m][6], sacc[m][7]};
            *reinterpret_cast<float4*>(&sS[(r0+m) * AP + c0    ]) = o0;
            *reinterpret_cast<float4*>(&sS[(r0+m) * AP + c0 + 4]) = o1;
        }
        __syncthreads();

        if (tid < 64) {
            float* srow = sS + tid * AP;
            float mx = -1e30f;
            #pragma unroll 8
            for (int j = 0; j < 64; j++) mx = fmaxf(mx, srow[j]);
            float mo = row_m[tid];
            float mn = fmaxf(mo, mx);
            float alpha = __expf(mo - mn);
            float sum = 0.f;
            #pragma unroll 8
            for (int j = 0; j < 64; j++) {
                float p = __expf(srow[j] - mn);
                srow[j] = p;
                sum += p;
            }
            row_l[tid] = row_l[tid] * alpha + sum;
            row_m[tid] = mn;
            row_alpha[tid] = alpha;
        }
        __syncthreads();

        float al[4];
        #pragma unroll
        for (int m = 0; m < 4; m++) al[m] = row_alpha[r0 + m];
        #pragma unroll
        for (int m = 0; m < 4; m++)
            #pragma unroll
            for (int n = 0; n < 8; n++) acc[m][n] *= al[m];

        #pragma unroll 8
        for (int j = 0; j < 64; j++) {
            float p[4];
            #pragma unroll
            for (int m = 0; m < 4; m++) p[m] = sS[(r0+m) * AP + j];
            float4 v0 = *reinterpret_cast<const float4*>(&sV[j * AP + c0]);
            float4 v1 = *reinterpret_cast<const float4*>(&sV[j * AP + c0 + 4]);
            float vb[8] = {v0.x, v0.y, v0.z, v0.w, v1.x, v1.y, v1.z, v1.w};
            #pragma unroll
            for (int m = 0; m < 4; m++)
                #pragma unroll
                for (int n = 0; n < 8; n++)
                    acc[m][n] += p[m] * vb[n];
        }
        __syncthreads();
    }

    float* Og = g_AO + ((size_t)b * T_LEN + q0) * D_MODEL + h * HEAD_DIM;
    #pragma unroll
    for (int m = 0; m < 4; m++) {
        int r = r0 + m;
        float inv = 1.0f / row_l[r];
        float4 o0, o1;
        o0.x = acc[m][0]*inv; o0.y = acc[m][1]*inv; o0.z = acc[m][2]*inv; o0.w = acc[m][3]*inv;
        o1.x = acc[m][4]*inv; o1.y = acc[m][5]*inv; o1.z = acc[m][6]*inv; o1.w = acc[m][7]*inv;
        *reinterpret_cast<float4*>(Og + (size_t)r * D_MODEL + c0    ) = o0;
        *reinterpret_cast<float4*>(Og + (size_t)r * D_MODEL + c0 + 4) = o1;
    }
}

// =================================================================
extern "C" void kernel_launch(void* const* d_in, const int* in_sizes, int n_in,
                              void* d_out, int out_size)
{
    const float* dec = (const float*)d_in[0];
    const float* enc = (const float*)d_in[1];
    const float* Wq  = (const float*)d_in[2];
    const float* bq  = (const float*)d_in[3];
    const float* Wk  = (const float*)d_in[4];
    const float* bk  = (const float*)d_in[5];
    const float* Wv  = (const float*)d_in[6];
    const float* bv  = (const float*)d_in[7];
    const float* Wo  = (const float*)d_in[8];
    const float* bo  = (const float*)d_in[9];
    float* out = (float*)d_out;

    const int GEMM_SMEM = 2 * STAGE_B;   // 110592
    cudaFuncSetAttribute(gemm_mma,
                         cudaFuncAttributeMaxDynamicSharedMemorySize, GEMM_SMEM);
    const int ATTN_SMEM = (4 * 64 * AP + 192) * (int)sizeof(float);
    cudaFuncSetAttribute(attention_kernel,
                         cudaFuncAttributeMaxDynamicSharedMemorySize, ATTN_SMEM);

    const int T_DEC = B_SZ * T_LEN * D_MODEL;
    const int T_ENC = B_SZ * S_LEN * D_MODEL;
    const int T_W   = D_MODEL * D_MODEL;

    conv_hilo<<<T_DEC / 1024, 256>>>(dec, 0, 0, T_DEC);
    conv_hilo<<<T_ENC / 1024, 256>>>(enc, 0, 1, T_ENC);
    conv_hilo<<<T_W   / 1024, 256>>>(Wq,  0, 3, T_W);
    conv_hilo<<<T_W   / 1024, 256>>>(Wk,  0, 4, T_W);
    conv_hilo<<<T_W   / 1024, 256>>>(Wv,  0, 5, T_W);
    conv_hilo<<<T_W   / 1024, 256>>>(Wo,  0, 6, T_W);

    // Q = dec @ Wq^T + bq
    gemm_mma<<<dim3(4, 32),  256, GEMM_SMEM>>>(0, 0, bq, nullptr, 0);
    // K = enc @ Wk^T + bk
    gemm_mma<<<dim3(4, 128), 256, GEMM_SMEM>>>(1, 1, bk, nullptr, 1);
    // V = enc @ Wv^T + bv
    gemm_mma<<<dim3(4, 128), 256, GEMM_SMEM>>>(1, 2, bv, nullptr, 2);

    // attention -> g_AO
    attention_kernel<<<dim3(T_LEN / 64, NUM_HEADS, B_SZ), 128, ATTN_SMEM>>>();

    // out = AO @ Wo^T + bo
    conv_hilo<<<T_DEC / 1024, 256>>>(nullptr, 1, 2, T_DEC);
    gemm_mma<<<dim3(4, 32),  256, GEMM_SMEM>>>(2, 3, bo, out, 3);
}